// round 13
// baseline (speedup 1.0000x reference)
#include <cuda_runtime.h>
#include <cuda_bf16.h>

// ---------------------------------------------------------------------------
// FrequencyFusion: STFT-magnitude -> conv1d(k=3) -> adaptive_avg_pool(1023->128)
//
// Key restructuring: conv and adaptive-pool are both linear in the magnitudes,
// so pool(conv(m)) == conv(pool(m)).  We therefore build the *pooled* im2col
// matrix P[K=1728][N=4096] directly from the STFT magnitudes (K = (c*9+f)*3+tap,
// N = b*128+i, already divided by the bin count), and do one GEMM:
//     out[n][m] = sum_k W[m][k] * P[k][n] + bias[m]
// which is 8x fewer FLOPs than conv-then-pool.
// ---------------------------------------------------------------------------

#define BATCH   32
#define LEN     4096
#define CH      64
#define HOP     4
#define T_FRAMES 1025          // 1 + LEN/HOP
#define FBINS   9
#define OUTW    128
#define OUTF    512
#define KDIM    1728           // 576 * 3
#define NDIM    4096           // BATCH * OUTW
#define CONV_T  1023           // T_FRAMES - 2

#define XS_LEN     4112        // LEN + 16 (reflect pad 8 each side)
#define MAG_STRIDE 1025
#define MAG_ROWS   5           // process f in two passes (5 + 4) to fit 48KB smem

__device__ float g_P[(size_t)KDIM * NDIM];   // 28.3 MB scratch

// cos(2*pi*j/16)
__device__ constexpr float COS16[16] = {
     1.0f,  0.9238795325112867f,  0.7071067811865476f,  0.3826834323650898f,
     0.0f, -0.3826834323650898f, -0.7071067811865476f, -0.9238795325112867f,
    -1.0f, -0.9238795325112867f, -0.7071067811865476f, -0.3826834323650898f,
     0.0f,  0.3826834323650898f,  0.7071067811865476f,  0.9238795325112867f
};
// periodic hann, win_len = 16
__device__ constexpr float HANN[16] = {
    0.0f,                 0.03806023374435663f, 0.14644660940672624f, 0.3086582838174551f,
    0.5f,                 0.6913417161825449f,  0.8535533905932737f,  0.9619397662556434f,
    1.0f,                 0.9619397662556434f,  0.8535533905932737f,  0.6913417161825449f,
    0.5f,                 0.3086582838174551f,  0.14644660940672624f, 0.03806023374435663f
};

// Compute magnitude rows for bins [F0, F0+NF) into mag[kk*MAG_STRIDE + t].
// Coefficients fold to immediates (F0, kk, n all compile-time after unroll).
template <int F0, int NF>
__device__ __forceinline__ void compute_mags(const float* xs, float* mag, int tid) {
    for (int t = tid; t < T_FRAMES; t += 256) {
        const int base = t * HOP;
        float v[16];
#pragma unroll
        for (int n = 0; n < 16; ++n) v[n] = xs[base + n] * HANN[n];
        float ae[8], bo[8];
#pragma unroll
        for (int n = 0; n < 8; ++n) { ae[n] = v[n] + v[n + 8]; bo[n] = v[n] - v[n + 8]; }
#pragma unroll
        for (int kk = 0; kk < NF; ++kk) {
            const int k = F0 + kk;              // compile-time under unroll
            float re = 0.f, im = 0.f;
#pragma unroll
            for (int n = 0; n < 8; ++n) {
                float s = (k & 1) ? bo[n] : ae[n];
                re += s * COS16[(k * n) & 15];         // cos term
                im += s * COS16[(k * n + 12) & 15];    // (-sin) term; sign irrelevant for |.|
            }
            mag[kk * MAG_STRIDE + t] = sqrtf(re * re + im * im);
        }
    }
}

// Pooled sums for bins [f0, f0+nf): P[(c*27 + f*3 + tap)][b*128 + i]
__device__ __forceinline__ void pool_mags(int f0, int nf, const float* mag,
                                          int b, int c, int tid) {
    const int total = nf * 3 * 128;
    for (int idx = tid; idx < total; idx += 256) {
        int i  = idx & 127;
        int jj = idx >> 7;          // 0 .. nf*3-1
        int fl = jj / 3;
        int tap = jj - fl * 3;
        int s0 = (i * CONV_T) >> 7;
        int e0 = ((i + 1) * CONV_T + 127) >> 7;
        float inv = 1.0f / (float)(e0 - s0);
        const float* mrow = mag + fl * MAG_STRIDE;
        float acc = 0.f;
        for (int t = s0 + tap; t < e0 + tap; ++t) acc += mrow[t];
        int kidx = c * 27 + (f0 + fl) * 3 + tap;
        g_P[(size_t)kidx * NDIM + (b << 7) + i] = acc * inv;
    }
}

__global__ __launch_bounds__(256)
void stft_pool_kernel(const float* __restrict__ x) {
    __shared__ float xs[XS_LEN];
    __shared__ float mag[MAG_ROWS * MAG_STRIDE];

    const int b = blockIdx.x >> 6;
    const int c = blockIdx.x & 63;
    const int tid = threadIdx.x;

    // Load one channel with reflect padding (pad = 8).
    const float* xb = x + (size_t)b * LEN * CH + c;
    for (int j = tid; j < XS_LEN; j += 256) {
        int i = j - 8;
        int r = (i < 0) ? -i : ((i >= LEN) ? (2 * LEN - 2 - i) : i);
        xs[j] = xb[(size_t)r * CH];
    }
    __syncthreads();

    compute_mags<0, 5>(xs, mag, tid);
    __syncthreads();
    pool_mags(0, 5, mag, b, c, tid);
    __syncthreads();
    compute_mags<5, 4>(xs, mag, tid);
    __syncthreads();
    pool_mags(5, 4, mag, b, c, tid);
}

// ---------------------------------------------------------------------------
// SGEMM: out[n][m] = sum_k W[m][k] * P[k][n] + bias[m]
//   M = 512, N = 4096, K = 1728.  128x128 tile, BK=16, 256 threads, 8x8/thread.
// ---------------------------------------------------------------------------
#define BM 128
#define BN 128
#define BKK 16
#define AS_STRIDE 132   // pad to reduce transpose-store conflicts

__global__ __launch_bounds__(256)
void gemm_kernel(const float* __restrict__ W,
                 const float* __restrict__ bias,
                 float* __restrict__ out) {
    __shared__ float As[BKK][AS_STRIDE];
    __shared__ float Bs[BKK][BN];

    const int bn = blockIdx.x;      // 0..31 (N tiles)
    const int bm = blockIdx.y;      // 0..3  (M tiles)
    const int tid = threadIdx.x;
    const int tx = tid & 15;
    const int ty = tid >> 4;

    const int arow  = tid >> 2;     // 0..63
    const int acol4 = tid & 3;      // float4 col within BK
    const int brow  = tid >> 5;     // 0..7
    const int bcol  = (tid & 31) << 2;

    const float* Ap = W + (size_t)(bm * BM) * KDIM;
    const float* Bp = g_P + (size_t)bn * BN;

    float acc[8][8];
#pragma unroll
    for (int i = 0; i < 8; ++i)
#pragma unroll
        for (int j = 0; j < 8; ++j) acc[i][j] = 0.f;

    for (int k0 = 0; k0 < KDIM; k0 += BKK) {
        // A tile (transpose into As[k][m])
#pragma unroll
        for (int h = 0; h < 2; ++h) {
            int r = arow + h * 64;
            float4 va = *(const float4*)(Ap + (size_t)r * KDIM + k0 + acol4 * 4);
            As[acol4 * 4 + 0][r] = va.x;
            As[acol4 * 4 + 1][r] = va.y;
            As[acol4 * 4 + 2][r] = va.z;
            As[acol4 * 4 + 3][r] = va.w;
        }
        // B tile (direct copy)
#pragma unroll
        for (int h = 0; h < 2; ++h) {
            int r = brow + h * 8;
            *(float4*)(&Bs[r][bcol]) =
                *(const float4*)(Bp + (size_t)(k0 + r) * NDIM + bcol);
        }
        __syncthreads();

#pragma unroll
        for (int k = 0; k < BKK; ++k) {
            float a[8], bq[8];
            *(float4*)(a)     = *(const float4*)(&As[k][ty * 4]);
            *(float4*)(a + 4) = *(const float4*)(&As[k][ty * 4 + 64]);
            *(float4*)(bq)     = *(const float4*)(&Bs[k][tx * 4]);
            *(float4*)(bq + 4) = *(const float4*)(&Bs[k][tx * 4 + 64]);
#pragma unroll
            for (int i = 0; i < 8; ++i)
#pragma unroll
                for (int j = 0; j < 8; ++j)
                    acc[i][j] += a[i] * bq[j];
        }
        __syncthreads();
    }

    // Epilogue: out[n*512 + m] = acc + bias[m]
    const int m0 = bm * BM + ty * 4;
    float bb[8];
#pragma unroll
    for (int i = 0; i < 4; ++i) {
        bb[i]     = bias[m0 + i];
        bb[i + 4] = bias[m0 + 64 + i];
    }
#pragma unroll
    for (int j = 0; j < 8; ++j) {
        int n = bn * BN + tx * 4 + ((j < 4) ? j : 60 + j);  // +64 group for j>=4
        float4 v0, v1;
        v0.x = acc[0][j] + bb[0]; v0.y = acc[1][j] + bb[1];
        v0.z = acc[2][j] + bb[2]; v0.w = acc[3][j] + bb[3];
        v1.x = acc[4][j] + bb[4]; v1.y = acc[5][j] + bb[5];
        v1.z = acc[6][j] + bb[6]; v1.w = acc[7][j] + bb[7];
        float* orow = out + (size_t)n * OUTF + m0;
        *(float4*)(orow)      = v0;
        *(float4*)(orow + 64) = v1;
    }
}

extern "C" void kernel_launch(void* const* d_in, const int* in_sizes, int n_in,
                              void* d_out, int out_size) {
    (void)in_sizes; (void)n_in; (void)out_size;
    const float* x    = (const float*)d_in[0];   // [32, 4096, 64]
    const float* w    = (const float*)d_in[1];   // [512, 576, 3] == [512, 1728]
    const float* bias = (const float*)d_in[2];   // [512]
    float* out = (float*)d_out;                  // [32, 128, 512]

    stft_pool_kernel<<<BATCH * CH, 256>>>(x);
    gemm_kernel<<<dim3(32, 4), 256>>>(w, bias, out);
}

// round 14
// speedup vs baseline: 1.0030x; 1.0030x over previous
#include <cuda_runtime.h>
#include <cuda_bf16.h>

// ---------------------------------------------------------------------------
// FrequencyFusion: STFT-magnitude -> conv1d(k=3) -> adaptive_avg_pool(1023->128)
//
// Key restructuring: conv and adaptive-pool are both linear in the magnitudes,
// so pool(conv(m)) == conv(pool(m)).  We therefore build the *pooled* im2col
// matrix P[K=1728][N=4096] directly from the STFT magnitudes (K = (c*9+f)*3+tap,
// N = b*128+i, already divided by the bin count), and do one GEMM:
//     out[n][m] = sum_k W[m][k] * P[k][n] + bias[m]
// which is 8x fewer FLOPs than conv-then-pool.
// ---------------------------------------------------------------------------

#define BATCH   32
#define LEN     4096
#define CH      64
#define HOP     4
#define T_FRAMES 1025          // 1 + LEN/HOP
#define FBINS   9
#define OUTW    128
#define OUTF    512
#define KDIM    1728           // 576 * 3
#define NDIM    4096           // BATCH * OUTW
#define CONV_T  1023           // T_FRAMES - 2

#define XS_LEN     4112        // LEN + 16 (reflect pad 8 each side)
#define MAG_STRIDE 1025
#define MAG_ROWS   5           // process f in two passes (5 + 4) to fit 48KB smem

__device__ float g_P[(size_t)KDIM * NDIM];   // 28.3 MB scratch

// cos(2*pi*j/16)
__device__ constexpr float COS16[16] = {
     1.0f,  0.9238795325112867f,  0.7071067811865476f,  0.3826834323650898f,
     0.0f, -0.3826834323650898f, -0.7071067811865476f, -0.9238795325112867f,
    -1.0f, -0.9238795325112867f, -0.7071067811865476f, -0.3826834323650898f,
     0.0f,  0.3826834323650898f,  0.7071067811865476f,  0.9238795325112867f
};
// periodic hann, win_len = 16
__device__ constexpr float HANN[16] = {
    0.0f,                 0.03806023374435663f, 0.14644660940672624f, 0.3086582838174551f,
    0.5f,                 0.6913417161825449f,  0.8535533905932737f,  0.9619397662556434f,
    1.0f,                 0.9619397662556434f,  0.8535533905932737f,  0.6913417161825449f,
    0.5f,                 0.3086582838174551f,  0.14644660940672624f, 0.03806023374435663f
};

// Compute magnitude rows for bins [F0, F0+NF) into mag[kk*MAG_STRIDE + t].
// Coefficients fold to immediates (F0, kk, n all compile-time after unroll).
template <int F0, int NF>
__device__ __forceinline__ void compute_mags(const float* xs, float* mag, int tid) {
    for (int t = tid; t < T_FRAMES; t += 256) {
        const int base = t * HOP;
        float v[16];
#pragma unroll
        for (int n = 0; n < 16; ++n) v[n] = xs[base + n] * HANN[n];
        float ae[8], bo[8];
#pragma unroll
        for (int n = 0; n < 8; ++n) { ae[n] = v[n] + v[n + 8]; bo[n] = v[n] - v[n + 8]; }
#pragma unroll
        for (int kk = 0; kk < NF; ++kk) {
            const int k = F0 + kk;              // compile-time under unroll
            float re = 0.f, im = 0.f;
#pragma unroll
            for (int n = 0; n < 8; ++n) {
                float s = (k & 1) ? bo[n] : ae[n];
                re += s * COS16[(k * n) & 15];         // cos term
                im += s * COS16[(k * n + 12) & 15];    // (-sin) term; sign irrelevant for |.|
            }
            mag[kk * MAG_STRIDE + t] = sqrtf(re * re + im * im);
        }
    }
}

// Pooled sums for bins [f0, f0+nf): P[(c*27 + f*3 + tap)][b*128 + i]
__device__ __forceinline__ void pool_mags(int f0, int nf, const float* mag,
                                          int b, int c, int tid) {
    const int total = nf * 3 * 128;
    for (int idx = tid; idx < total; idx += 256) {
        int i  = idx & 127;
        int jj = idx >> 7;          // 0 .. nf*3-1
        int fl = jj / 3;
        int tap = jj - fl * 3;
        int s0 = (i * CONV_T) >> 7;
        int e0 = ((i + 1) * CONV_T + 127) >> 7;
        float inv = 1.0f / (float)(e0 - s0);
        const float* mrow = mag + fl * MAG_STRIDE;
        float acc = 0.f;
        for (int t = s0 + tap; t < e0 + tap; ++t) acc += mrow[t];
        int kidx = c * 27 + (f0 + fl) * 3 + tap;
        g_P[(size_t)kidx * NDIM + (b << 7) + i] = acc * inv;
    }
}

__global__ __launch_bounds__(256)
void stft_pool_kernel(const float* __restrict__ x) {
    __shared__ float xs[XS_LEN];
    __shared__ float mag[MAG_ROWS * MAG_STRIDE];

    const int b = blockIdx.x >> 6;
    const int c = blockIdx.x & 63;
    const int tid = threadIdx.x;

    // Load one channel with reflect padding (pad = 8).
    const float* xb = x + (size_t)b * LEN * CH + c;
    for (int j = tid; j < XS_LEN; j += 256) {
        int i = j - 8;
        int r = (i < 0) ? -i : ((i >= LEN) ? (2 * LEN - 2 - i) : i);
        xs[j] = xb[(size_t)r * CH];
    }
    __syncthreads();

    compute_mags<0, 5>(xs, mag, tid);
    __syncthreads();
    pool_mags(0, 5, mag, b, c, tid);
    __syncthreads();
    compute_mags<5, 4>(xs, mag, tid);
    __syncthreads();
    pool_mags(5, 4, mag, b, c, tid);
}

// ---------------------------------------------------------------------------
// SGEMM: out[n][m] = sum_k W[m][k] * P[k][n] + bias[m]
//   M = 512, N = 4096, K = 1728.  128x128 tile, BK=16, 256 threads, 8x8/thread.
// ---------------------------------------------------------------------------
#define BM 128
#define BN 128
#define BKK 16
#define AS_STRIDE 132   // pad to reduce transpose-store conflicts

__global__ __launch_bounds__(256)
void gemm_kernel(const float* __restrict__ W,
                 const float* __restrict__ bias,
                 float* __restrict__ out) {
    __shared__ float As[BKK][AS_STRIDE];
    __shared__ float Bs[BKK][BN];

    const int bn = blockIdx.x;      // 0..31 (N tiles)
    const int bm = blockIdx.y;      // 0..3  (M tiles)
    const int tid = threadIdx.x;
    const int tx = tid & 15;
    const int ty = tid >> 4;

    const int arow  = tid >> 2;     // 0..63
    const int acol4 = tid & 3;      // float4 col within BK
    const int brow  = tid >> 5;     // 0..7
    const int bcol  = (tid & 31) << 2;

    const float* Ap = W + (size_t)(bm * BM) * KDIM;
    const float* Bp = g_P + (size_t)bn * BN;

    float acc[8][8];
#pragma unroll
    for (int i = 0; i < 8; ++i)
#pragma unroll
        for (int j = 0; j < 8; ++j) acc[i][j] = 0.f;

    for (int k0 = 0; k0 < KDIM; k0 += BKK) {
        // A tile (transpose into As[k][m])
#pragma unroll
        for (int h = 0; h < 2; ++h) {
            int r = arow + h * 64;
            float4 va = *(const float4*)(Ap + (size_t)r * KDIM + k0 + acol4 * 4);
            As[acol4 * 4 + 0][r] = va.x;
            As[acol4 * 4 + 1][r] = va.y;
            As[acol4 * 4 + 2][r] = va.z;
            As[acol4 * 4 + 3][r] = va.w;
        }
        // B tile (direct copy)
#pragma unroll
        for (int h = 0; h < 2; ++h) {
            int r = brow + h * 8;
            *(float4*)(&Bs[r][bcol]) =
                *(const float4*)(Bp + (size_t)(k0 + r) * NDIM + bcol);
        }
        __syncthreads();

#pragma unroll
        for (int k = 0; k < BKK; ++k) {
            float a[8], bq[8];
            *(float4*)(a)     = *(const float4*)(&As[k][ty * 4]);
            *(float4*)(a + 4) = *(const float4*)(&As[k][ty * 4 + 64]);
            *(float4*)(bq)     = *(const float4*)(&Bs[k][tx * 4]);
            *(float4*)(bq + 4) = *(const float4*)(&Bs[k][tx * 4 + 64]);
#pragma unroll
            for (int i = 0; i < 8; ++i)
#pragma unroll
                for (int j = 0; j < 8; ++j)
                    acc[i][j] += a[i] * bq[j];
        }
        __syncthreads();
    }

    // Epilogue: out[n*512 + m] = acc + bias[m]
    const int m0 = bm * BM + ty * 4;
    float bb[8];
#pragma unroll
    for (int i = 0; i < 4; ++i) {
        bb[i]     = bias[m0 + i];
        bb[i + 4] = bias[m0 + 64 + i];
    }
#pragma unroll
    for (int j = 0; j < 8; ++j) {
        int n = bn * BN + tx * 4 + ((j < 4) ? j : 60 + j);  // +64 group for j>=4
        float4 v0, v1;
        v0.x = acc[0][j] + bb[0]; v0.y = acc[1][j] + bb[1];
        v0.z = acc[2][j] + bb[2]; v0.w = acc[3][j] + bb[3];
        v1.x = acc[4][j] + bb[4]; v1.y = acc[5][j] + bb[5];
        v1.z = acc[6][j] + bb[6]; v1.w = acc[7][j] + bb[7];
        float* orow = out + (size_t)n * OUTF + m0;
        *(float4*)(orow)      = v0;
        *(float4*)(orow + 64) = v1;
    }
}

extern "C" void kernel_launch(void* const* d_in, const int* in_sizes, int n_in,
                              void* d_out, int out_size) {
    (void)in_sizes; (void)n_in; (void)out_size;
    const float* x    = (const float*)d_in[0];   // [32, 4096, 64]
    const float* w    = (const float*)d_in[1];   // [512, 576, 3] == [512, 1728]
    const float* bias = (const float*)d_in[2];   // [512]
    float* out = (float*)d_out;                  // [32, 128, 512]

    stft_pool_kernel<<<BATCH * CH, 256>>>(x);
    gemm_kernel<<<dim3(32, 4), 256>>>(w, bias, out);
}

// round 15
// speedup vs baseline: 1.0059x; 1.0029x over previous
#include <cuda_runtime.h>
#include <cuda_bf16.h>

// ---------------------------------------------------------------------------
// FrequencyFusion: STFT-magnitude -> conv1d(k=3) -> adaptive_avg_pool(1023->128)
//
// Key restructuring: conv and adaptive-pool are both linear in the magnitudes,
// so pool(conv(m)) == conv(pool(m)).  We therefore build the *pooled* im2col
// matrix P[K=1728][N=4096] directly from the STFT magnitudes (K = (c*9+f)*3+tap,
// N = b*128+i, already divided by the bin count), and do one GEMM:
//     out[n][m] = sum_k W[m][k] * P[k][n] + bias[m]
// which is 8x fewer FLOPs than conv-then-pool.
// ---------------------------------------------------------------------------

#define BATCH   32
#define LEN     4096
#define CH      64
#define HOP     4
#define T_FRAMES 1025          // 1 + LEN/HOP
#define FBINS   9
#define OUTW    128
#define OUTF    512
#define KDIM    1728           // 576 * 3
#define NDIM    4096           // BATCH * OUTW
#define CONV_T  1023           // T_FRAMES - 2

#define XS_LEN     4112        // LEN + 16 (reflect pad 8 each side)
#define MAG_STRIDE 1025
#define MAG_ROWS   5           // process f in two passes (5 + 4) to fit 48KB smem

__device__ float g_P[(size_t)KDIM * NDIM];   // 28.3 MB scratch

// cos(2*pi*j/16)
__device__ constexpr float COS16[16] = {
     1.0f,  0.9238795325112867f,  0.7071067811865476f,  0.3826834323650898f,
     0.0f, -0.3826834323650898f, -0.7071067811865476f, -0.9238795325112867f,
    -1.0f, -0.9238795325112867f, -0.7071067811865476f, -0.3826834323650898f,
     0.0f,  0.3826834323650898f,  0.7071067811865476f,  0.9238795325112867f
};
// periodic hann, win_len = 16
__device__ constexpr float HANN[16] = {
    0.0f,                 0.03806023374435663f, 0.14644660940672624f, 0.3086582838174551f,
    0.5f,                 0.6913417161825449f,  0.8535533905932737f,  0.9619397662556434f,
    1.0f,                 0.9619397662556434f,  0.8535533905932737f,  0.6913417161825449f,
    0.5f,                 0.3086582838174551f,  0.14644660940672624f, 0.03806023374435663f
};

// Compute magnitude rows for bins [F0, F0+NF) into mag[kk*MAG_STRIDE + t].
// Coefficients fold to immediates (F0, kk, n all compile-time after unroll).
template <int F0, int NF>
__device__ __forceinline__ void compute_mags(const float* xs, float* mag, int tid) {
    for (int t = tid; t < T_FRAMES; t += 256) {
        const int base = t * HOP;
        float v[16];
#pragma unroll
        for (int n = 0; n < 16; ++n) v[n] = xs[base + n] * HANN[n];
        float ae[8], bo[8];
#pragma unroll
        for (int n = 0; n < 8; ++n) { ae[n] = v[n] + v[n + 8]; bo[n] = v[n] - v[n + 8]; }
#pragma unroll
        for (int kk = 0; kk < NF; ++kk) {
            const int k = F0 + kk;              // compile-time under unroll
            float re = 0.f, im = 0.f;
#pragma unroll
            for (int n = 0; n < 8; ++n) {
                float s = (k & 1) ? bo[n] : ae[n];
                re += s * COS16[(k * n) & 15];         // cos term
                im += s * COS16[(k * n + 12) & 15];    // (-sin) term; sign irrelevant for |.|
            }
            mag[kk * MAG_STRIDE + t] = sqrtf(re * re + im * im);
        }
    }
}

// Pooled sums for bins [f0, f0+nf): P[(c*27 + f*3 + tap)][b*128 + i]
__device__ __forceinline__ void pool_mags(int f0, int nf, const float* mag,
                                          int b, int c, int tid) {
    const int total = nf * 3 * 128;
    for (int idx = tid; idx < total; idx += 256) {
        int i  = idx & 127;
        int jj = idx >> 7;          // 0 .. nf*3-1
        int fl = jj / 3;
        int tap = jj - fl * 3;
        int s0 = (i * CONV_T) >> 7;
        int e0 = ((i + 1) * CONV_T + 127) >> 7;
        float inv = 1.0f / (float)(e0 - s0);
        const float* mrow = mag + fl * MAG_STRIDE;
        float acc = 0.f;
        for (int t = s0 + tap; t < e0 + tap; ++t) acc += mrow[t];
        int kidx = c * 27 + (f0 + fl) * 3 + tap;
        g_P[(size_t)kidx * NDIM + (b << 7) + i] = acc * inv;
    }
}

__global__ __launch_bounds__(256)
void stft_pool_kernel(const float* __restrict__ x) {
    __shared__ float xs[XS_LEN];
    __shared__ float mag[MAG_ROWS * MAG_STRIDE];

    const int b = blockIdx.x >> 6;
    const int c = blockIdx.x & 63;
    const int tid = threadIdx.x;

    // Load one channel with reflect padding (pad = 8).
    const float* xb = x + (size_t)b * LEN * CH + c;
    for (int j = tid; j < XS_LEN; j += 256) {
        int i = j - 8;
        int r = (i < 0) ? -i : ((i >= LEN) ? (2 * LEN - 2 - i) : i);
        xs[j] = xb[(size_t)r * CH];
    }
    __syncthreads();

    compute_mags<0, 5>(xs, mag, tid);
    __syncthreads();
    pool_mags(0, 5, mag, b, c, tid);
    __syncthreads();
    compute_mags<5, 4>(xs, mag, tid);
    __syncthreads();
    pool_mags(5, 4, mag, b, c, tid);
}

// ---------------------------------------------------------------------------
// SGEMM: out[n][m] = sum_k W[m][k] * P[k][n] + bias[m]
//   M = 512, N = 4096, K = 1728.  128x128 tile, BK=16, 256 threads, 8x8/thread.
// ---------------------------------------------------------------------------
#define BM 128
#define BN 128
#define BKK 16
#define AS_STRIDE 132   // pad to reduce transpose-store conflicts

__global__ __launch_bounds__(256)
void gemm_kernel(const float* __restrict__ W,
                 const float* __restrict__ bias,
                 float* __restrict__ out) {
    __shared__ float As[BKK][AS_STRIDE];
    __shared__ float Bs[BKK][BN];

    const int bn = blockIdx.x;      // 0..31 (N tiles)
    const int bm = blockIdx.y;      // 0..3  (M tiles)
    const int tid = threadIdx.x;
    const int tx = tid & 15;
    const int ty = tid >> 4;

    const int arow  = tid >> 2;     // 0..63
    const int acol4 = tid & 3;      // float4 col within BK
    const int brow  = tid >> 5;     // 0..7
    const int bcol  = (tid & 31) << 2;

    const float* Ap = W + (size_t)(bm * BM) * KDIM;
    const float* Bp = g_P + (size_t)bn * BN;

    float acc[8][8];
#pragma unroll
    for (int i = 0; i < 8; ++i)
#pragma unroll
        for (int j = 0; j < 8; ++j) acc[i][j] = 0.f;

    for (int k0 = 0; k0 < KDIM; k0 += BKK) {
        // A tile (transpose into As[k][m])
#pragma unroll
        for (int h = 0; h < 2; ++h) {
            int r = arow + h * 64;
            float4 va = *(const float4*)(Ap + (size_t)r * KDIM + k0 + acol4 * 4);
            As[acol4 * 4 + 0][r] = va.x;
            As[acol4 * 4 + 1][r] = va.y;
            As[acol4 * 4 + 2][r] = va.z;
            As[acol4 * 4 + 3][r] = va.w;
        }
        // B tile (direct copy)
#pragma unroll
        for (int h = 0; h < 2; ++h) {
            int r = brow + h * 8;
            *(float4*)(&Bs[r][bcol]) =
                *(const float4*)(Bp + (size_t)(k0 + r) * NDIM + bcol);
        }
        __syncthreads();

#pragma unroll
        for (int k = 0; k < BKK; ++k) {
            float a[8], bq[8];
            *(float4*)(a)     = *(const float4*)(&As[k][ty * 4]);
            *(float4*)(a + 4) = *(const float4*)(&As[k][ty * 4 + 64]);
            *(float4*)(bq)     = *(const float4*)(&Bs[k][tx * 4]);
            *(float4*)(bq + 4) = *(const float4*)(&Bs[k][tx * 4 + 64]);
#pragma unroll
            for (int i = 0; i < 8; ++i)
#pragma unroll
                for (int j = 0; j < 8; ++j)
                    acc[i][j] += a[i] * bq[j];
        }
        __syncthreads();
    }

    // Epilogue: out[n*512 + m] = acc + bias[m]
    const int m0 = bm * BM + ty * 4;
    float bb[8];
#pragma unroll
    for (int i = 0; i < 4; ++i) {
        bb[i]     = bias[m0 + i];
        bb[i + 4] = bias[m0 + 64 + i];
    }
#pragma unroll
    for (int j = 0; j < 8; ++j) {
        int n = bn * BN + tx * 4 + ((j < 4) ? j : 60 + j);  // +64 group for j>=4
        float4 v0, v1;
        v0.x = acc[0][j] + bb[0]; v0.y = acc[1][j] + bb[1];
        v0.z = acc[2][j] + bb[2]; v0.w = acc[3][j] + bb[3];
        v1.x = acc[4][j] + bb[4]; v1.y = acc[5][j] + bb[5];
        v1.z = acc[6][j] + bb[6]; v1.w = acc[7][j] + bb[7];
        float* orow = out + (size_t)n * OUTF + m0;
        *(float4*)(orow)      = v0;
        *(float4*)(orow + 64) = v1;
    }
}

extern "C" void kernel_launch(void* const* d_in, const int* in_sizes, int n_in,
                              void* d_out, int out_size) {
    (void)in_sizes; (void)n_in; (void)out_size;
    const float* x    = (const float*)d_in[0];   // [32, 4096, 64]
    const float* w    = (const float*)d_in[1];   // [512, 576, 3] == [512, 1728]
    const float* bias = (const float*)d_in[2];   // [512]
    float* out = (float*)d_out;                  // [32, 128, 512]

    stft_pool_kernel<<<BATCH * CH, 256>>>(x);
    gemm_kernel<<<dim3(32, 4), 256>>>(w, bias, out);
}

// round 16
// speedup vs baseline: 1.1020x; 1.0955x over previous
#include <cuda_runtime.h>
#include <cuda_bf16.h>

// ---------------------------------------------------------------------------
// FrequencyFusion: STFT-magnitude -> conv1d(k=3) -> adaptive_avg_pool(1023->128)
// pool(conv(m)) == conv(pool(m)) -> build pooled im2col P[1728][4096], one GEMM.
// This round: (1) GEMM inner product in packed fma.rn.f32x2 (2x fp32 pipe),
//             (2) STFT blocks process 2 channels via float2 (halve LDG wavefronts).
// ---------------------------------------------------------------------------

#define BATCH   32
#define LEN     4096
#define CH      64
#define HOP     4
#define T_FRAMES 1025
#define FBINS   9
#define OUTW    128
#define OUTF    512
#define KDIM    1728
#define NDIM    4096
#define CONV_T  1023

#define XS_LEN     4112        // LEN + 16 (reflect pad 8 each side)
#define MAG_STRIDE 1025
#define MAG_ROWS   3

__device__ float g_P[(size_t)KDIM * NDIM];   // 28.3 MB scratch

// cos(2*pi*j/16)
__device__ constexpr float COS16[16] = {
     1.0f,  0.9238795325112867f,  0.7071067811865476f,  0.3826834323650898f,
     0.0f, -0.3826834323650898f, -0.7071067811865476f, -0.9238795325112867f,
    -1.0f, -0.9238795325112867f, -0.7071067811865476f, -0.3826834323650898f,
     0.0f,  0.3826834323650898f,  0.7071067811865476f,  0.9238795325112867f
};
// periodic hann, win_len = 16
__device__ constexpr float HANN[16] = {
    0.0f,                 0.03806023374435663f, 0.14644660940672624f, 0.3086582838174551f,
    0.5f,                 0.6913417161825449f,  0.8535533905932737f,  0.9619397662556434f,
    1.0f,                 0.9619397662556434f,  0.8535533905932737f,  0.6913417161825449f,
    0.5f,                 0.3086582838174551f,  0.14644660940672624f, 0.03806023374435663f
};

template <int F0, int NF>
__device__ __forceinline__ void compute_mags(const float* xs, float* mag, int tid) {
    for (int t = tid; t < T_FRAMES; t += 256) {
        const int base = t * HOP;
        float v[16];
#pragma unroll
        for (int n = 0; n < 16; ++n) v[n] = xs[base + n] * HANN[n];
        float ae[8], bo[8];
#pragma unroll
        for (int n = 0; n < 8; ++n) { ae[n] = v[n] + v[n + 8]; bo[n] = v[n] - v[n + 8]; }
#pragma unroll
        for (int kk = 0; kk < NF; ++kk) {
            const int k = F0 + kk;
            float re = 0.f, im = 0.f;
#pragma unroll
            for (int n = 0; n < 8; ++n) {
                float s = (k & 1) ? bo[n] : ae[n];
                re += s * COS16[(k * n) & 15];
                im += s * COS16[(k * n + 12) & 15];
            }
            mag[kk * MAG_STRIDE + t] = sqrtf(re * re + im * im);
        }
    }
}

__device__ __forceinline__ void pool_mags(int f0, int nf, const float* mag,
                                          int b, int c, int tid) {
    const int total = nf * 3 * 128;
    for (int idx = tid; idx < total; idx += 256) {
        int i  = idx & 127;
        int jj = idx >> 7;
        int fl = jj / 3;
        int tap = jj - fl * 3;
        int s0 = (i * CONV_T) >> 7;
        int e0 = ((i + 1) * CONV_T + 127) >> 7;
        float inv = 1.0f / (float)(e0 - s0);
        const float* mrow = mag + fl * MAG_STRIDE;
        float acc = 0.f;
        for (int t = s0 + tap; t < e0 + tap; ++t) acc += mrow[t];
        int kidx = c * 27 + (f0 + fl) * 3 + tap;
        g_P[(size_t)kidx * NDIM + (b << 7) + i] = acc * inv;
    }
}

// One block handles (b, channel pair). float2 loads halve LDG wavefront count.
__global__ __launch_bounds__(256)
void stft_pool_kernel(const float* __restrict__ x) {
    __shared__ float xs[2][XS_LEN];
    __shared__ float mag[MAG_ROWS * MAG_STRIDE];

    const int b  = blockIdx.x >> 5;
    const int c0 = (blockIdx.x & 31) << 1;
    const int tid = threadIdx.x;

    const float* xb = x + (size_t)b * LEN * CH + c0;
    for (int j = tid; j < XS_LEN; j += 256) {
        int i = j - 8;
        int r = (i < 0) ? -i : ((i >= LEN) ? (2 * LEN - 2 - i) : i);
        float2 v = *(const float2*)(xb + (size_t)r * CH);
        xs[0][j] = v.x;
        xs[1][j] = v.y;
    }
    __syncthreads();

#pragma unroll
    for (int ch = 0; ch < 2; ++ch) {
        const float* xsc = xs[ch];
        const int c = c0 + ch;
        compute_mags<0, 3>(xsc, mag, tid); __syncthreads();
        pool_mags(0, 3, mag, b, c, tid);   __syncthreads();
        compute_mags<3, 3>(xsc, mag, tid); __syncthreads();
        pool_mags(3, 3, mag, b, c, tid);   __syncthreads();
        compute_mags<6, 3>(xsc, mag, tid); __syncthreads();
        pool_mags(6, 3, mag, b, c, tid);   __syncthreads();
    }
}

// ---------------------------------------------------------------------------
// SGEMM with packed f32x2 FMAs: out[n][m] = sum_k W[m][k] * P[k][n] + bias[m]
//   M=512, N=4096, K=1728. 128x128 tile, BK=16, 256 threads, 8x8/thread.
// ---------------------------------------------------------------------------
#define BM 128
#define BN 128
#define BKK 16
#define AS_STRIDE 132

__device__ __forceinline__ unsigned long long pack_dup(float a) {
    unsigned long long r;
    asm("mov.b64 %0, {%1, %1};" : "=l"(r) : "f"(a));
    return r;
}
__device__ __forceinline__ unsigned long long pack2(float lo, float hi) {
    unsigned long long r;
    asm("mov.b64 %0, {%1, %2};" : "=l"(r) : "f"(lo), "f"(hi));
    return r;
}
__device__ __forceinline__ void unpack2(unsigned long long v, float& lo, float& hi) {
    asm("mov.b64 {%0, %1}, %2;" : "=f"(lo), "=f"(hi) : "l"(v));
}
#define FFMA2(d, a, b) \
    asm("fma.rn.f32x2 %0, %1, %2, %0;" : "+l"(d) : "l"(a), "l"(b))

__global__ __launch_bounds__(256)
void gemm_kernel(const float* __restrict__ W,
                 const float* __restrict__ bias,
                 float* __restrict__ out) {
    __shared__ float As[BKK][AS_STRIDE];
    __shared__ float Bs[BKK][BN];

    const int bn = blockIdx.x;      // 0..31
    const int bm = blockIdx.y;      // 0..3
    const int tid = threadIdx.x;
    const int tx = tid & 15;
    const int ty = tid >> 4;

    const int arow  = tid >> 2;
    const int acol4 = tid & 3;
    const int brow  = tid >> 5;
    const int bcol  = (tid & 31) << 2;

    const float* Ap = W + (size_t)(bm * BM) * KDIM;
    const float* Bp = g_P + (size_t)bn * BN;

    unsigned long long acc2[8][4];
#pragma unroll
    for (int i = 0; i < 8; ++i)
#pragma unroll
        for (int jp = 0; jp < 4; ++jp) acc2[i][jp] = 0ull;

    for (int k0 = 0; k0 < KDIM; k0 += BKK) {
#pragma unroll
        for (int h = 0; h < 2; ++h) {
            int r = arow + h * 64;
            float4 va = *(const float4*)(Ap + (size_t)r * KDIM + k0 + acol4 * 4);
            As[acol4 * 4 + 0][r] = va.x;
            As[acol4 * 4 + 1][r] = va.y;
            As[acol4 * 4 + 2][r] = va.z;
            As[acol4 * 4 + 3][r] = va.w;
        }
#pragma unroll
        for (int h = 0; h < 2; ++h) {
            int r = brow + h * 8;
            *(float4*)(&Bs[r][bcol]) =
                *(const float4*)(Bp + (size_t)(k0 + r) * NDIM + bcol);
        }
        __syncthreads();

#pragma unroll
        for (int k = 0; k < BKK; ++k) {
            float a[8];
            *(float4*)(a)     = *(const float4*)(&As[k][ty * 4]);
            *(float4*)(a + 4) = *(const float4*)(&As[k][ty * 4 + 64]);
            float4 bq0 = *(const float4*)(&Bs[k][tx * 4]);
            float4 bq1 = *(const float4*)(&Bs[k][tx * 4 + 64]);

            unsigned long long b2[4];
            b2[0] = pack2(bq0.x, bq0.y);
            b2[1] = pack2(bq0.z, bq0.w);
            b2[2] = pack2(bq1.x, bq1.y);
            b2[3] = pack2(bq1.z, bq1.w);

            unsigned long long a2[8];
#pragma unroll
            for (int i = 0; i < 8; ++i) a2[i] = pack_dup(a[i]);

#pragma unroll
            for (int i = 0; i < 8; ++i)
#pragma unroll
                for (int jp = 0; jp < 4; ++jp)
                    FFMA2(acc2[i][jp], a2[i], b2[jp]);
        }
        __syncthreads();
    }

    // Unpack accumulators: acc[i][j], j = 2*jp + half
    float accf[8][8];
#pragma unroll
    for (int i = 0; i < 8; ++i)
#pragma unroll
        for (int jp = 0; jp < 4; ++jp)
            unpack2(acc2[i][jp], accf[i][2 * jp], accf[i][2 * jp + 1]);

    const int m0 = bm * BM + ty * 4;
    float bb[8];
#pragma unroll
    for (int i = 0; i < 4; ++i) {
        bb[i]     = bias[m0 + i];
        bb[i + 4] = bias[m0 + 64 + i];
    }
#pragma unroll
    for (int j = 0; j < 8; ++j) {
        int n = bn * BN + tx * 4 + ((j < 4) ? j : 60 + j);  // +64 group for j>=4
        float4 v0, v1;
        v0.x = accf[0][j] + bb[0]; v0.y = accf[1][j] + bb[1];
        v0.z = accf[2][j] + bb[2]; v0.w = accf[3][j] + bb[3];
        v1.x = accf[4][j] + bb[4]; v1.y = accf[5][j] + bb[5];
        v1.z = accf[6][j] + bb[6]; v1.w = accf[7][j] + bb[7];
        float* orow = out + (size_t)n * OUTF + m0;
        *(float4*)(orow)      = v0;
        *(float4*)(orow + 64) = v1;
    }
}

extern "C" void kernel_launch(void* const* d_in, const int* in_sizes, int n_in,
                              void* d_out, int out_size) {
    (void)in_sizes; (void)n_in; (void)out_size;
    const float* x    = (const float*)d_in[0];   // [32, 4096, 64]
    const float* w    = (const float*)d_in[1];   // [512, 576, 3] == [512, 1728]
    const float* bias = (const float*)d_in[2];   // [512]
    float* out = (float*)d_out;                  // [32, 128, 512]

    stft_pool_kernel<<<BATCH * (CH / 2), 256>>>(x);
    gemm_kernel<<<dim3(32, 4), 256>>>(w, bias, out);
}